// round 2
// baseline (speedup 1.0000x reference)
#include <cuda_runtime.h>
#include <math.h>

// Problem constants
#define PIXELS 8192      // B*H*W = 8*32*32
#define DD 512
#define FF 32
#define NN 16384
#define HWSZ 1024
#define SPLITS 8
#define CPS (NN / SPLITS)   // 2048 codes per split
#define CHUNK 256           // codes per shared tile in kernel C

// Output layout (concatenated flattened outputs, float32):
#define OUT_OFF      0
#define CLOSEST_OFF  4194304
#define LOSS_OFF     4202496
#define PERP_OFF     4202497

// Scratch (no allocations allowed)
__device__ float g_xn[PIXELS * FF];       // normalized projected x, [p][32]
__device__ float g_en[NN * FF];           // normalized codebook, [n][32]
__device__ float g_pval[SPLITS * PIXELS]; // per-split best value
__device__ int   g_pidx[SPLITS * PIXELS]; // per-split best index
__device__ int   g_closest[PIXELS];
__device__ int   g_hist[NN];
__device__ float g_lossp[PIXELS];

// ---------------------------------------------------------------------------
// Kernel A: 1x1 conv projection + channel L2 normalize.
// ---------------------------------------------------------------------------
__global__ void proj_norm_kernel(const float* __restrict__ enc,
                                 const float* __restrict__ pw,
                                 const float* __restrict__ pb)
{
    extern __shared__ float sm[];
    float* Ws  = sm;                 // 32*512
    float* xsh = sm + FF * DD;       // 32*33 (padded)
    float* nrm = xsh + 32 * 33;      // 32

    int tid = threadIdx.x;

    const float4* W4 = (const float4*)pw;
    float4* Ws4 = (float4*)Ws;
#pragma unroll
    for (int i = 0; i < 16; i++) Ws4[tid + 256 * i] = W4[tid + 256 * i];
    __syncthreads();

    int lane = tid & 31;     // pixel within tile
    int fg   = tid >> 5;     // 0..7
    int f0   = fg * 4;
    int p    = blockIdx.x * 32 + lane;
    int b    = p >> 10;
    int hw   = p & 1023;

    const float* ep = enc + (size_t)b * DD * HWSZ + hw;
    const float4* w0 = (const float4*)(Ws + (size_t)(f0 + 0) * DD);
    const float4* w1 = (const float4*)(Ws + (size_t)(f0 + 1) * DD);
    const float4* w2 = (const float4*)(Ws + (size_t)(f0 + 2) * DD);
    const float4* w3 = (const float4*)(Ws + (size_t)(f0 + 3) * DD);

    float a0 = 0.f, a1 = 0.f, a2 = 0.f, a3 = 0.f;
#pragma unroll 4
    for (int q = 0; q < 128; q++) {
        float e0 = ep[(4 * q + 0) * HWSZ];
        float e1 = ep[(4 * q + 1) * HWSZ];
        float e2 = ep[(4 * q + 2) * HWSZ];
        float e3 = ep[(4 * q + 3) * HWSZ];
        float4 W0 = w0[q], W1 = w1[q], W2 = w2[q], W3 = w3[q];
        a0 += e0 * W0.x; a0 += e1 * W0.y; a0 += e2 * W0.z; a0 += e3 * W0.w;
        a1 += e0 * W1.x; a1 += e1 * W1.y; a1 += e2 * W1.z; a1 += e3 * W1.w;
        a2 += e0 * W2.x; a2 += e1 * W2.y; a2 += e2 * W2.z; a2 += e3 * W2.w;
        a3 += e0 * W3.x; a3 += e1 * W3.y; a3 += e2 * W3.z; a3 += e3 * W3.w;
    }
    a0 += pb[f0 + 0];
    a1 += pb[f0 + 1];
    a2 += pb[f0 + 2];
    a3 += pb[f0 + 3];

    xsh[lane * 33 + f0 + 0] = a0;
    xsh[lane * 33 + f0 + 1] = a1;
    xsh[lane * 33 + f0 + 2] = a2;
    xsh[lane * 33 + f0 + 3] = a3;
    __syncthreads();

    if (tid < 32) {
        float ss = 0.f;
#pragma unroll
        for (int f = 0; f < 32; f++) { float v = xsh[tid * 33 + f]; ss += v * v; }
        nrm[tid] = fmaxf(sqrtf(ss), 1e-6f);
    }
    __syncthreads();

    float nm = nrm[lane];
    float4 o;
    o.x = a0 / nm; o.y = a1 / nm; o.z = a2 / nm; o.w = a3 / nm;
    *(float4*)(g_xn + (size_t)p * FF + f0) = o;
}

// ---------------------------------------------------------------------------
// Kernel B: codebook L2 normalize (warp per row) + zero histogram.
// ---------------------------------------------------------------------------
__global__ void enorm_kernel(const float* __restrict__ emb)
{
    int tid  = threadIdx.x;
    int r    = blockIdx.x * 8 + (tid >> 5);
    int lane = tid & 31;
    float v = emb[(size_t)r * 32 + lane];
    float ss = v * v;
#pragma unroll
    for (int o = 16; o; o >>= 1) ss += __shfl_xor_sync(0xffffffffu, ss, o);
    float nm = fmaxf(sqrtf(ss), 1e-6f);
    g_en[(size_t)r * 32 + lane] = v / nm;
    if (tid < 8) g_hist[blockIdx.x * 8 + tid] = 0;
}

// ---------------------------------------------------------------------------
// Kernel C (dominant): fused cosine-sims GEMM + running argmax, on packed
// fp32x2 FMA (FFMA2) — 2 exact fp32 MACs per issued instruction.
// Block: 256 threads = 16 tx (code pair groups) x 16 ty (pixel groups of 8).
// Block tile: 128 pixels x 256 codes per chunk; thread tile 8 px x 16 codes.
// grid (64 pixel tiles, 8 code splits)
// ---------------------------------------------------------------------------
__global__ void __launch_bounds__(256, 2) sims_argmax_kernel()
{
    extern __shared__ float dynsm[];
    float* xs = dynsm;                  // [128][33] padded
    float* es = dynsm + 128 * 33;       // [32][256] transposed e tile

    int tid   = threadIdx.x;
    int px0   = blockIdx.x * 128;
    int cbase = blockIdx.y * CPS;

    // load x tile (128 pixels x 32 f)
    for (int i = tid; i < 1024; i += 256) {
        int pp = i >> 3;
        int f0 = (i & 7) * 4;
        float4 v = *(const float4*)(g_xn + (size_t)(px0 + pp) * 32 + f0);
        xs[pp * 33 + f0 + 0] = v.x;
        xs[pp * 33 + f0 + 1] = v.y;
        xs[pp * 33 + f0 + 2] = v.z;
        xs[pp * 33 + f0 + 3] = v.w;
    }

    int tx = tid & 15;
    int ty = tid >> 4;
    float bv[8];
    int   bi[8];
#pragma unroll
    for (int i = 0; i < 8; i++) { bv[i] = -3.4e38f; bi[i] = 0; }

    for (int ch = 0; ch < CPS; ch += CHUNK) {
        __syncthreads();
        // load e chunk transposed: es[f][c] = e_norm[cbase+ch+c][f]
        {
            const float4* src = (const float4*)(g_en + (size_t)(cbase + ch + tid) * 32);
#pragma unroll
            for (int q = 0; q < 8; q++) {
                float4 v = src[q];
                es[(q * 4 + 0) * CHUNK + tid] = v.x;
                es[(q * 4 + 1) * CHUNK + tid] = v.y;
                es[(q * 4 + 2) * CHUNK + tid] = v.z;
                es[(q * 4 + 3) * CHUNK + tid] = v.w;
            }
        }
        __syncthreads();

        unsigned long long acc[8][8];
#pragma unroll
        for (int i = 0; i < 8; i++)
#pragma unroll
            for (int j = 0; j < 8; j++) acc[i][j] = 0ull;

#pragma unroll 4
        for (int f = 0; f < 32; f++) {
            unsigned long long ev[8];
#pragma unroll
            for (int j = 0; j < 8; j++)
                ev[j] = *(const unsigned long long*)(es + f * CHUNK + tx * 2 + 32 * j);
#pragma unroll
            for (int i = 0; i < 8; i++) {
                float xv = xs[(ty * 8 + i) * 33 + f];
                unsigned long long xp;
                asm("mov.b64 %0, {%1, %1};" : "=l"(xp) : "f"(xv));
#pragma unroll
                for (int j = 0; j < 8; j++)
                    asm("fma.rn.f32x2 %0, %1, %2, %0;"
                        : "+l"(acc[i][j]) : "l"(xp), "l"(ev[j]));
            }
        }

        // argmax update; ascending code order (j asc, lo then hi) keeps
        // first occurrence within this thread, matching jnp.argmax tie-break
#pragma unroll
        for (int j = 0; j < 8; j++) {
            int cg = cbase + ch + tx * 2 + 32 * j;
#pragma unroll
            for (int i = 0; i < 8; i++) {
                float lo, hi;
                asm("mov.b64 {%0, %1}, %2;" : "=f"(lo), "=f"(hi) : "l"(acc[i][j]));
                if (lo > bv[i]) { bv[i] = lo; bi[i] = cg; }
                if (hi > bv[i]) { bv[i] = hi; bi[i] = cg + 1; }
            }
        }
    }

    // cross-tx reduction in shared (reuse es buffer)
    __syncthreads();
    float* rv = es;                  // [128][16] floats
    int*   ri = (int*)(es + 2048);   // [128][16] ints
#pragma unroll
    for (int i = 0; i < 8; i++) {
        rv[(ty * 8 + i) * 16 + tx] = bv[i];
        ri[(ty * 8 + i) * 16 + tx] = bi[i];
    }
    __syncthreads();
    if (tid < 128) {
        float v = -3.4e38f;
        int ix = 0x7fffffff;
#pragma unroll
        for (int k = 0; k < 16; k++) {
            float vv = rv[tid * 16 + k];
            int   ii = ri[tid * 16 + k];
            if (vv > v || (vv == v && ii < ix)) { v = vv; ix = ii; }
        }
        g_pval[blockIdx.y * PIXELS + px0 + tid] = v;
        g_pidx[blockIdx.y * PIXELS + px0 + tid] = ix;
    }
}

// ---------------------------------------------------------------------------
// Kernel F: reduce split partials -> closest; histogram; per-pixel loss partial.
// ---------------------------------------------------------------------------
__global__ void reduce_kernel(float* __restrict__ out)
{
    int p = blockIdx.x * 256 + threadIdx.x;
    float bv = -3.4e38f;
    int   bi = 0x7fffffff;
#pragma unroll
    for (int s = 0; s < SPLITS; s++) {
        float v = g_pval[s * PIXELS + p];
        int  ix = g_pidx[s * PIXELS + p];
        if (v > bv || (v == bv && ix < bi)) { bv = v; bi = ix; }
    }
    g_closest[p] = bi;
    out[CLOSEST_OFF + p] = (float)bi;
    atomicAdd(&g_hist[bi], 1);

    float s2 = 0.f;
    const float4* xr = (const float4*)(g_xn + (size_t)p * 32);
    const float4* er = (const float4*)(g_en + (size_t)bi * 32);
#pragma unroll
    for (int q = 0; q < 8; q++) {
        float4 x = xr[q], e = er[q];
        float d0 = x.x - e.x, d1 = x.y - e.y, d2 = x.z - e.z, d3 = x.w - e.w;
        s2 += d0 * d0; s2 += d1 * d1; s2 += d2 * d2; s2 += d3 * d3;
    }
    g_lossp[p] = s2;
}

// ---------------------------------------------------------------------------
// Kernel D: expansion GEMM: out[b,d,hw] = sum_f lat[p][f] * exp_w[d][f] + exp_b[d]
// ---------------------------------------------------------------------------
__global__ void expand_kernel(const float* __restrict__ ew,
                              const float* __restrict__ eb,
                              float* __restrict__ out)
{
    __shared__ float Wsh[64 * 32];
    __shared__ float bsh[64];
    int tid = threadIdx.x;
    int d0  = blockIdx.y * 64;

    const float4* src = (const float4*)(ew + (size_t)d0 * 32);
    float4* dst = (float4*)Wsh;
    dst[tid]       = src[tid];
    dst[tid + 256] = src[tid + 256];
    if (tid < 64) bsh[tid] = eb[d0 + tid];
    __syncthreads();

    int p  = blockIdx.x * 256 + tid;
    int b  = p >> 10;
    int hw = p & 1023;
    int idx = g_closest[p];

    float4 lat[8];
    const float4* lr = (const float4*)(g_en + (size_t)idx * 32);
#pragma unroll
    for (int q = 0; q < 8; q++) lat[q] = lr[q];

    float* outp = out + OUT_OFF + ((size_t)b * 512 + d0) * 1024 + hw;
#pragma unroll 2
    for (int dd = 0; dd < 64; dd++) {
        const float4* wr = (const float4*)(Wsh + dd * 32);
        float s = bsh[dd];
#pragma unroll
        for (int q = 0; q < 8; q++) {
            float4 w = wr[q];
            s += lat[q].x * w.x; s += lat[q].y * w.y;
            s += lat[q].z * w.z; s += lat[q].w * w.w;
        }
        outp[(size_t)dd * 1024] = s;
    }
}

// ---------------------------------------------------------------------------
// Kernel G: deterministic final reductions -> loss_q, perplexity
// ---------------------------------------------------------------------------
__global__ void finalize_kernel(float* __restrict__ out)
{
    __shared__ double sh[256];
    int tid = threadIdx.x;

    double ls = 0.0;
    for (int i = tid; i < PIXELS; i += 256) ls += (double)g_lossp[i];
    sh[tid] = ls;
    __syncthreads();
    for (int o = 128; o; o >>= 1) {
        if (tid < o) sh[tid] += sh[tid + o];
        __syncthreads();
    }
    double loss = sh[0] / (double)(PIXELS * 32);
    __syncthreads();

    double ps = 0.0;
    for (int i = tid; i < NN; i += 256) {
        float u = (float)g_hist[i] * (1.0f / 8192.0f);
        ps += -(double)u * log((double)u + 1e-6);
    }
    sh[tid] = ps;
    __syncthreads();
    for (int o = 128; o; o >>= 1) {
        if (tid < o) sh[tid] += sh[tid + o];
        __syncthreads();
    }
    if (tid == 0) {
        out[LOSS_OFF] = (float)loss;
        out[PERP_OFF] = (float)exp(sh[0]);
    }
}

// ---------------------------------------------------------------------------
extern "C" void kernel_launch(void* const* d_in, const int* in_sizes, int n_in,
                              void* d_out, int out_size)
{
    const float* enc = (const float*)d_in[0];  // [8,512,32,32]
    const float* emb = (const float*)d_in[1];  // [16384,32]
    const float* pw  = (const float*)d_in[2];  // [32,512]
    const float* pb  = (const float*)d_in[3];  // [32]
    const float* ew  = (const float*)d_in[4];  // [512,32]
    const float* eb  = (const float*)d_in[5];  // [512]
    float* out = (float*)d_out;

    (void)in_sizes; (void)n_in; (void)out_size;

    const int a_smem = (FF * DD + 32 * 33 + 32) * (int)sizeof(float); // 69888
    cudaFuncSetAttribute(proj_norm_kernel,
                         cudaFuncAttributeMaxDynamicSharedMemorySize, a_smem);

    const int c_smem = (128 * 33 + 32 * CHUNK) * (int)sizeof(float);  // 49664
    cudaFuncSetAttribute(sims_argmax_kernel,
                         cudaFuncAttributeMaxDynamicSharedMemorySize, c_smem);

    proj_norm_kernel<<<256, 256, a_smem>>>(enc, pw, pb);
    enorm_kernel<<<2048, 256>>>(emb);
    sims_argmax_kernel<<<dim3(64, SPLITS), 256, c_smem>>>();
    reduce_kernel<<<32, 256>>>(out);
    expand_kernel<<<dim3(32, 8), 256>>>(ew, eb, out);
    finalize_kernel<<<1, 256>>>(out);
}

// round 3
// speedup vs baseline: 3.5122x; 3.5122x over previous
#include <cuda_runtime.h>
#include <math.h>

// Problem constants
#define PIXELS 8192      // B*H*W = 8*32*32
#define DD 512
#define FF 32
#define NN 16384
#define HWSZ 1024
#define SPLITS 8
#define CPS (NN / SPLITS)   // 2048 codes per split
#define CHUNK 256           // codes per shared tile in kernel C
#define PXT 64              // pixels per block in kernel C

// Output layout (concatenated flattened outputs, float32):
#define OUT_OFF      0
#define CLOSEST_OFF  4194304
#define LOSS_OFF     4202496
#define PERP_OFF     4202497

// Scratch (no allocations allowed)
__device__ float g_xn[PIXELS * FF];       // normalized projected x, [p][32]
__device__ float g_en[NN * FF];           // normalized codebook, [n][32]
__device__ float g_pval[SPLITS * PIXELS]; // per-split best value
__device__ int   g_pidx[SPLITS * PIXELS]; // per-split best index
__device__ int   g_closest[PIXELS];
__device__ int   g_hist[NN];
__device__ float g_lossp[PIXELS];

// ---------------------------------------------------------------------------
// Kernel A: 1x1 conv projection + channel L2 normalize.
// ---------------------------------------------------------------------------
__global__ void proj_norm_kernel(const float* __restrict__ enc,
                                 const float* __restrict__ pw,
                                 const float* __restrict__ pb)
{
    extern __shared__ float sm[];
    float* Ws  = sm;                 // 32*512
    float* xsh = sm + FF * DD;       // 32*33 (padded)
    float* nrm = xsh + 32 * 33;      // 32

    int tid = threadIdx.x;

    const float4* W4 = (const float4*)pw;
    float4* Ws4 = (float4*)Ws;
#pragma unroll
    for (int i = 0; i < 16; i++) Ws4[tid + 256 * i] = W4[tid + 256 * i];
    __syncthreads();

    int lane = tid & 31;     // pixel within tile
    int fg   = tid >> 5;     // 0..7
    int f0   = fg * 4;
    int p    = blockIdx.x * 32 + lane;
    int b    = p >> 10;
    int hw   = p & 1023;

    const float* ep = enc + (size_t)b * DD * HWSZ + hw;
    const float4* w0 = (const float4*)(Ws + (size_t)(f0 + 0) * DD);
    const float4* w1 = (const float4*)(Ws + (size_t)(f0 + 1) * DD);
    const float4* w2 = (const float4*)(Ws + (size_t)(f0 + 2) * DD);
    const float4* w3 = (const float4*)(Ws + (size_t)(f0 + 3) * DD);

    float a0 = 0.f, a1 = 0.f, a2 = 0.f, a3 = 0.f;
#pragma unroll 4
    for (int q = 0; q < 128; q++) {
        float e0 = ep[(4 * q + 0) * HWSZ];
        float e1 = ep[(4 * q + 1) * HWSZ];
        float e2 = ep[(4 * q + 2) * HWSZ];
        float e3 = ep[(4 * q + 3) * HWSZ];
        float4 W0 = w0[q], W1 = w1[q], W2 = w2[q], W3 = w3[q];
        a0 += e0 * W0.x; a0 += e1 * W0.y; a0 += e2 * W0.z; a0 += e3 * W0.w;
        a1 += e0 * W1.x; a1 += e1 * W1.y; a1 += e2 * W1.z; a1 += e3 * W1.w;
        a2 += e0 * W2.x; a2 += e1 * W2.y; a2 += e2 * W2.z; a2 += e3 * W2.w;
        a3 += e0 * W3.x; a3 += e1 * W3.y; a3 += e2 * W3.z; a3 += e3 * W3.w;
    }
    a0 += pb[f0 + 0];
    a1 += pb[f0 + 1];
    a2 += pb[f0 + 2];
    a3 += pb[f0 + 3];

    xsh[lane * 33 + f0 + 0] = a0;
    xsh[lane * 33 + f0 + 1] = a1;
    xsh[lane * 33 + f0 + 2] = a2;
    xsh[lane * 33 + f0 + 3] = a3;
    __syncthreads();

    if (tid < 32) {
        float ss = 0.f;
#pragma unroll
        for (int f = 0; f < 32; f++) { float v = xsh[tid * 33 + f]; ss += v * v; }
        nrm[tid] = fmaxf(sqrtf(ss), 1e-6f);
    }
    __syncthreads();

    float nm = nrm[lane];
    float4 o;
    o.x = a0 / nm; o.y = a1 / nm; o.z = a2 / nm; o.w = a3 / nm;
    *(float4*)(g_xn + (size_t)p * FF + f0) = o;
}

// ---------------------------------------------------------------------------
// Kernel B: codebook L2 normalize (warp per row) + zero histogram.
// ---------------------------------------------------------------------------
__global__ void enorm_kernel(const float* __restrict__ emb)
{
    int tid  = threadIdx.x;
    int r    = blockIdx.x * 8 + (tid >> 5);
    int lane = tid & 31;
    float v = emb[(size_t)r * 32 + lane];
    float ss = v * v;
#pragma unroll
    for (int o = 16; o; o >>= 1) ss += __shfl_xor_sync(0xffffffffu, ss, o);
    float nm = fmaxf(sqrtf(ss), 1e-6f);
    g_en[(size_t)r * 32 + lane] = v / nm;
    if (tid < 8) g_hist[blockIdx.x * 8 + tid] = 0;
}

// ---------------------------------------------------------------------------
// Kernel C (dominant): fused cosine-sims GEMM + running argmax on packed
// fp32x2 FMA (FFMA2). Thread tile 4 px x 16 codes (64 u64 accumulators —
// fits the 128-reg cap; R2's 8x8 tile spilled).
// Block: 256 threads = 16 tx (code pair groups) x 16 ty (4-pixel groups).
// Block tile: 64 pixels x 256-code chunks. grid (128 pixel tiles, 8 splits)
// ---------------------------------------------------------------------------
__global__ void __launch_bounds__(256, 2) sims_argmax_kernel()
{
    extern __shared__ float dynsm[];
    float* xs = dynsm;                  // [64][33] padded
    float* es = dynsm + PXT * 33;       // [32][256] transposed e tile

    int tid   = threadIdx.x;
    int px0   = blockIdx.x * PXT;
    int cbase = blockIdx.y * CPS;

    // load x tile (64 pixels x 32 f)
    for (int i = tid; i < PXT * 8; i += 256) {
        int pp = i >> 3;
        int f0 = (i & 7) * 4;
        float4 v = *(const float4*)(g_xn + (size_t)(px0 + pp) * 32 + f0);
        xs[pp * 33 + f0 + 0] = v.x;
        xs[pp * 33 + f0 + 1] = v.y;
        xs[pp * 33 + f0 + 2] = v.z;
        xs[pp * 33 + f0 + 3] = v.w;
    }

    int tx = tid & 15;
    int ty = tid >> 4;
    float bv[4];
    int   bi[4];
#pragma unroll
    for (int i = 0; i < 4; i++) { bv[i] = -3.4e38f; bi[i] = 0; }

    for (int ch = 0; ch < CPS; ch += CHUNK) {
        __syncthreads();
        // load e chunk transposed: es[f][c] = e_norm[cbase+ch+c][f]
        {
            const float4* src = (const float4*)(g_en + (size_t)(cbase + ch + tid) * 32);
#pragma unroll
            for (int q = 0; q < 8; q++) {
                float4 v = src[q];
                es[(q * 4 + 0) * CHUNK + tid] = v.x;
                es[(q * 4 + 1) * CHUNK + tid] = v.y;
                es[(q * 4 + 2) * CHUNK + tid] = v.z;
                es[(q * 4 + 3) * CHUNK + tid] = v.w;
            }
        }
        __syncthreads();

        unsigned long long acc[4][8];
#pragma unroll
        for (int i = 0; i < 4; i++)
#pragma unroll
            for (int j = 0; j < 8; j++) acc[i][j] = 0ull;

#pragma unroll 2
        for (int f = 0; f < 32; f++) {
            unsigned long long ev[8];
#pragma unroll
            for (int j = 0; j < 8; j++)
                ev[j] = *(const unsigned long long*)(es + f * CHUNK + tx * 2 + 32 * j);
#pragma unroll
            for (int i = 0; i < 4; i++) {
                float xv = xs[(ty * 4 + i) * 33 + f];
                unsigned long long xp;
                asm("mov.b64 %0, {%1, %1};" : "=l"(xp) : "f"(xv));
#pragma unroll
                for (int j = 0; j < 8; j++)
                    asm("fma.rn.f32x2 %0, %1, %2, %0;"
                        : "+l"(acc[i][j]) : "l"(xp), "l"(ev[j]));
            }
        }

        // argmax update; ascending code order (j asc, lo then hi) keeps
        // first occurrence within this thread, matching jnp.argmax tie-break
#pragma unroll
        for (int j = 0; j < 8; j++) {
            int cg = cbase + ch + tx * 2 + 32 * j;
#pragma unroll
            for (int i = 0; i < 4; i++) {
                float lo, hi;
                asm("mov.b64 {%0, %1}, %2;" : "=f"(lo), "=f"(hi) : "l"(acc[i][j]));
                if (lo > bv[i]) { bv[i] = lo; bi[i] = cg; }
                if (hi > bv[i]) { bv[i] = hi; bi[i] = cg + 1; }
            }
        }
    }

    // cross-tx reduction in shared (reuse es buffer)
    __syncthreads();
    float* rv = es;                  // [64][16] floats
    int*   ri = (int*)(es + 1024);   // [64][16] ints
#pragma unroll
    for (int i = 0; i < 4; i++) {
        rv[(ty * 4 + i) * 16 + tx] = bv[i];
        ri[(ty * 4 + i) * 16 + tx] = bi[i];
    }
    __syncthreads();
    if (tid < PXT) {
        float v = -3.4e38f;
        int ix = 0x7fffffff;
#pragma unroll
        for (int k = 0; k < 16; k++) {
            float vv = rv[tid * 16 + k];
            int   ii = ri[tid * 16 + k];
            if (vv > v || (vv == v && ii < ix)) { v = vv; ix = ii; }
        }
        g_pval[blockIdx.y * PIXELS + px0 + tid] = v;
        g_pidx[blockIdx.y * PIXELS + px0 + tid] = ix;
    }
}

// ---------------------------------------------------------------------------
// Kernel F: reduce split partials -> closest; histogram; per-pixel loss partial.
// ---------------------------------------------------------------------------
__global__ void reduce_kernel(float* __restrict__ out)
{
    int p = blockIdx.x * 256 + threadIdx.x;
    float bv = -3.4e38f;
    int   bi = 0x7fffffff;
#pragma unroll
    for (int s = 0; s < SPLITS; s++) {
        float v = g_pval[s * PIXELS + p];
        int  ix = g_pidx[s * PIXELS + p];
        if (v > bv || (v == bv && ix < bi)) { bv = v; bi = ix; }
    }
    g_closest[p] = bi;
    out[CLOSEST_OFF + p] = (float)bi;
    atomicAdd(&g_hist[bi], 1);

    float s2 = 0.f;
    const float4* xr = (const float4*)(g_xn + (size_t)p * 32);
    const float4* er = (const float4*)(g_en + (size_t)bi * 32);
#pragma unroll
    for (int q = 0; q < 8; q++) {
        float4 x = xr[q], e = er[q];
        float d0 = x.x - e.x, d1 = x.y - e.y, d2 = x.z - e.z, d3 = x.w - e.w;
        s2 += d0 * d0; s2 += d1 * d1; s2 += d2 * d2; s2 += d3 * d3;
    }
    g_lossp[p] = s2;
}

// ---------------------------------------------------------------------------
// Kernel D: expansion GEMM: out[b,d,hw] = sum_f lat[p][f] * exp_w[d][f] + exp_b[d]
// ---------------------------------------------------------------------------
__global__ void expand_kernel(const float* __restrict__ ew,
                              const float* __restrict__ eb,
                              float* __restrict__ out)
{
    __shared__ float Wsh[64 * 32];
    __shared__ float bsh[64];
    int tid = threadIdx.x;
    int d0  = blockIdx.y * 64;

    const float4* src = (const float4*)(ew + (size_t)d0 * 32);
    float4* dst = (float4*)Wsh;
    dst[tid]       = src[tid];
    dst[tid + 256] = src[tid + 256];
    if (tid < 64) bsh[tid] = eb[d0 + tid];
    __syncthreads();

    int p  = blockIdx.x * 256 + tid;
    int b  = p >> 10;
    int hw = p & 1023;
    int idx = g_closest[p];

    float4 lat[8];
    const float4* lr = (const float4*)(g_en + (size_t)idx * 32);
#pragma unroll
    for (int q = 0; q < 8; q++) lat[q] = lr[q];

    float* outp = out + OUT_OFF + ((size_t)b * 512 + d0) * 1024 + hw;
#pragma unroll 2
    for (int dd = 0; dd < 64; dd++) {
        const float4* wr = (const float4*)(Wsh + dd * 32);
        float s = bsh[dd];
#pragma unroll
        for (int q = 0; q < 8; q++) {
            float4 w = wr[q];
            s += lat[q].x * w.x; s += lat[q].y * w.y;
            s += lat[q].z * w.z; s += lat[q].w * w.w;
        }
        outp[(size_t)dd * 1024] = s;
    }
}

// ---------------------------------------------------------------------------
// Kernel G: deterministic final reductions -> loss_q, perplexity
// ---------------------------------------------------------------------------
__global__ void finalize_kernel(float* __restrict__ out)
{
    __shared__ double sh[256];
    int tid = threadIdx.x;

    double ls = 0.0;
    for (int i = tid; i < PIXELS; i += 256) ls += (double)g_lossp[i];
    sh[tid] = ls;
    __syncthreads();
    for (int o = 128; o; o >>= 1) {
        if (tid < o) sh[tid] += sh[tid + o];
        __syncthreads();
    }
    double loss = sh[0] / (double)(PIXELS * 32);
    __syncthreads();

    double ps = 0.0;
    for (int i = tid; i < NN; i += 256) {
        float u = (float)g_hist[i] * (1.0f / 8192.0f);
        ps += -(double)u * log((double)u + 1e-6);
    }
    sh[tid] = ps;
    __syncthreads();
    for (int o = 128; o; o >>= 1) {
        if (tid < o) sh[tid] += sh[tid + o];
        __syncthreads();
    }
    if (tid == 0) {
        out[LOSS_OFF] = (float)loss;
        out[PERP_OFF] = (float)exp(sh[0]);
    }
}

// ---------------------------------------------------------------------------
extern "C" void kernel_launch(void* const* d_in, const int* in_sizes, int n_in,
                              void* d_out, int out_size)
{
    const float* enc = (const float*)d_in[0];  // [8,512,32,32]
    const float* emb = (const float*)d_in[1];  // [16384,32]
    const float* pw  = (const float*)d_in[2];  // [32,512]
    const float* pb  = (const float*)d_in[3];  // [32]
    const float* ew  = (const float*)d_in[4];  // [512,32]
    const float* eb  = (const float*)d_in[5];  // [512]
    float* out = (float*)d_out;

    (void)in_sizes; (void)n_in; (void)out_size;

    const int a_smem = (FF * DD + 32 * 33 + 32) * (int)sizeof(float); // 69888
    cudaFuncSetAttribute(proj_norm_kernel,
                         cudaFuncAttributeMaxDynamicSharedMemorySize, a_smem);

    const int c_smem = (PXT * 33 + 32 * CHUNK) * (int)sizeof(float);  // 41216
    cudaFuncSetAttribute(sims_argmax_kernel,
                         cudaFuncAttributeMaxDynamicSharedMemorySize, c_smem);

    proj_norm_kernel<<<256, 256, a_smem>>>(enc, pw, pb);
    enorm_kernel<<<2048, 256>>>(emb);
    sims_argmax_kernel<<<dim3(128, SPLITS), 256, c_smem>>>();
    reduce_kernel<<<32, 256>>>(out);
    expand_kernel<<<dim3(32, 8), 256>>>(ew, eb, out);
    finalize_kernel<<<1, 256>>>(out);
}

// round 6
// speedup vs baseline: 3.8276x; 1.0898x over previous
#include <cuda_runtime.h>
#include <cuda_bf16.h>
#include <cstdint>
#include <math.h>

// Problem constants
#define PIXELS 8192      // B*H*W = 8*32*32
#define DD 512
#define FF 32
#define NN 16384
#define HWSZ 1024
#define SPLITS 8
#define CPS (NN / SPLITS)   // 2048 codes per split
#define KS2 192             // 6 split blocks of 32 along K
#define NKT 12              // k16 steps per dot product
#define XSTR2 200           // smem row stride in bf16 (400B; banks conflict-free)
#define CH 64               // codes per chunk in kernel C

// Output layout (concatenated flattened outputs, float32):
#define OUT_OFF      0
#define CLOSEST_OFF  4194304
#define LOSS_OFF     4202496
#define PERP_OFF     4202497

// Scratch (no allocations allowed)
__device__ float g_xn[PIXELS * FF];       // normalized projected x, [p][32]
__device__ float g_en[NN * FF];           // normalized codebook, [n][32]
__device__ __nv_bfloat16 g_xsplit[PIXELS * KS2]; // [xh|xh|xm|xm|xh|xl]
__device__ __nv_bfloat16 g_esplit[NN * KS2];     // [eh|em|eh|em|el|eh]
__device__ float g_pval[SPLITS * PIXELS]; // per-split best value
__device__ int   g_pidx[SPLITS * PIXELS]; // per-split best index
__device__ int   g_closest[PIXELS];
__device__ int   g_hist[NN];
__device__ float g_lossp[PIXELS];

// exact fp32 -> bf16 x3 split (3 x 8 mantissa bits)
__device__ __forceinline__ void split3(float v, __nv_bfloat16& b0,
                                       __nv_bfloat16& b1, __nv_bfloat16& b2)
{
    b0 = __float2bfloat16_rn(v);
    float r1 = v - __bfloat162float(b0);
    b1 = __float2bfloat16_rn(r1);
    float r2 = r1 - __bfloat162float(b1);
    b2 = __float2bfloat16_rn(r2);
}

// ---------------------------------------------------------------------------
// Kernel A: 1x1 conv projection + channel L2 normalize + split layout.
// ---------------------------------------------------------------------------
__global__ void proj_norm_kernel(const float* __restrict__ enc,
                                 const float* __restrict__ pw,
                                 const float* __restrict__ pb)
{
    extern __shared__ float sm[];
    float* Ws  = sm;                 // 32*512
    float* xsh = sm + FF * DD;       // 32*33 (padded)
    float* nrm = xsh + 32 * 33;      // 32

    int tid = threadIdx.x;

    const float4* W4 = (const float4*)pw;
    float4* Ws4 = (float4*)Ws;
#pragma unroll
    for (int i = 0; i < 16; i++) Ws4[tid + 256 * i] = W4[tid + 256 * i];
    __syncthreads();

    int lane = tid & 31;     // pixel within tile
    int fg   = tid >> 5;     // 0..7
    int f0   = fg * 4;
    int p    = blockIdx.x * 32 + lane;
    int b    = p >> 10;
    int hw   = p & 1023;

    const float* ep = enc + (size_t)b * DD * HWSZ + hw;
    const float4* w0 = (const float4*)(Ws + (size_t)(f0 + 0) * DD);
    const float4* w1 = (const float4*)(Ws + (size_t)(f0 + 1) * DD);
    const float4* w2 = (const float4*)(Ws + (size_t)(f0 + 2) * DD);
    const float4* w3 = (const float4*)(Ws + (size_t)(f0 + 3) * DD);

    float a0 = 0.f, a1 = 0.f, a2 = 0.f, a3 = 0.f;
#pragma unroll 4
    for (int q = 0; q < 128; q++) {
        float e0 = ep[(4 * q + 0) * HWSZ];
        float e1 = ep[(4 * q + 1) * HWSZ];
        float e2 = ep[(4 * q + 2) * HWSZ];
        float e3 = ep[(4 * q + 3) * HWSZ];
        float4 W0 = w0[q], W1 = w1[q], W2 = w2[q], W3 = w3[q];
        a0 += e0 * W0.x; a0 += e1 * W0.y; a0 += e2 * W0.z; a0 += e3 * W0.w;
        a1 += e0 * W1.x; a1 += e1 * W1.y; a1 += e2 * W1.z; a1 += e3 * W1.w;
        a2 += e0 * W2.x; a2 += e1 * W2.y; a2 += e2 * W2.z; a2 += e3 * W2.w;
        a3 += e0 * W3.x; a3 += e1 * W3.y; a3 += e2 * W3.z; a3 += e3 * W3.w;
    }
    a0 += pb[f0 + 0];
    a1 += pb[f0 + 1];
    a2 += pb[f0 + 2];
    a3 += pb[f0 + 3];

    xsh[lane * 33 + f0 + 0] = a0;
    xsh[lane * 33 + f0 + 1] = a1;
    xsh[lane * 33 + f0 + 2] = a2;
    xsh[lane * 33 + f0 + 3] = a3;
    __syncthreads();

    if (tid < 32) {
        float ss = 0.f;
#pragma unroll
        for (int f = 0; f < 32; f++) { float v = xsh[tid * 33 + f]; ss += v * v; }
        nrm[tid] = fmaxf(sqrtf(ss), 1e-6f);
    }
    __syncthreads();

    float nm = nrm[lane];
    float o[4] = { a0 / nm, a1 / nm, a2 / nm, a3 / nm };
    *(float4*)(g_xn + (size_t)p * FF + f0) = *(float4*)o;

    // X split blocks: [xh | xh | xm | xm | xh | xl]
    __nv_bfloat16* xr = g_xsplit + (size_t)p * KS2;
#pragma unroll
    for (int k = 0; k < 4; k++) {
        __nv_bfloat16 h, m, l;
        split3(o[k], h, m, l);
        int f = f0 + k;
        xr[f]        = h;
        xr[32 + f]   = h;
        xr[64 + f]   = m;
        xr[96 + f]   = m;
        xr[128 + f]  = h;
        xr[160 + f]  = l;
    }
}

// ---------------------------------------------------------------------------
// Kernel B: codebook L2 normalize + split + zero histogram.
// ---------------------------------------------------------------------------
__global__ void enorm_kernel(const float* __restrict__ emb)
{
    int tid  = threadIdx.x;
    int r    = blockIdx.x * 8 + (tid >> 5);
    int lane = tid & 31;
    float v = emb[(size_t)r * 32 + lane];
    float ss = v * v;
#pragma unroll
    for (int o = 16; o; o >>= 1) ss += __shfl_xor_sync(0xffffffffu, ss, o);
    float nm = fmaxf(sqrtf(ss), 1e-6f);
    float en = v / nm;
    g_en[(size_t)r * 32 + lane] = en;

    // E split blocks: [eh | em | eh | em | el | eh]
    __nv_bfloat16 h, m, l;
    split3(en, h, m, l);
    __nv_bfloat16* er = g_esplit + (size_t)r * KS2;
    er[lane]        = h;
    er[32 + lane]   = m;
    er[64 + lane]   = h;
    er[96 + lane]   = m;
    er[128 + lane]  = l;
    er[160 + lane]  = h;

    if (tid < 8) g_hist[blockIdx.x * 8 + tid] = 0;
}

// ---------------------------------------------------------------------------
// mma.sync m16n8k16 row.col bf16 -> f32
// ---------------------------------------------------------------------------
__device__ __forceinline__ void mma16816(float* c, const uint32_t* a,
                                         uint32_t b0, uint32_t b1)
{
    asm volatile(
        "mma.sync.aligned.m16n8k16.row.col.f32.bf16.bf16.f32 "
        "{%0,%1,%2,%3}, {%4,%5,%6,%7}, {%8,%9}, {%0,%1,%2,%3};"
        : "+f"(c[0]), "+f"(c[1]), "+f"(c[2]), "+f"(c[3])
        : "r"(a[0]), "r"(a[1]), "r"(a[2]), "r"(a[3]), "r"(b0), "r"(b1));
}

// ---------------------------------------------------------------------------
// Kernel C (dominant): bf16 6-term split cosine sims on tensor cores
// (mma.sync) + running per-pixel argmax.
// Block 128 thr (4 warps). Block tile 128 px x 64-code chunks; warp = 32 px
// (two m16 tiles), K = 192 (12 k16 steps). grid (64 px-tiles, 8 splits).
// ---------------------------------------------------------------------------
__global__ void __launch_bounds__(128) sims_argmax_kernel()
{
    extern __shared__ __nv_bfloat16 smc[];
    __nv_bfloat16* xs = smc;                    // [128][XSTR2]
    __nv_bfloat16* es = smc + 128 * XSTR2;      // [64][XSTR2]

    int tid  = threadIdx.x;
    int wid  = tid >> 5;
    int lane = tid & 31;
    int g    = lane >> 2;   // row group / B column
    int kq   = lane & 3;    // k quad
    int px0  = blockIdx.x * 128;
    int cbase = blockIdx.y * CPS;

    // load x tile: 128 rows x 24 uint4 (384B/row)
    for (int i = tid; i < 128 * 24; i += 128) {
        int r = i / 24, q = i % 24;
        ((uint4*)(xs + r * XSTR2))[q] =
            ((const uint4*)(g_xsplit + (size_t)(px0 + r) * KS2))[q];
    }

    float bv[4];
    int   bi[4];
#pragma unroll
    for (int s = 0; s < 4; s++) { bv[s] = -3.4e38f; bi[s] = 0; }

    for (int ch = 0; ch < CPS; ch += CH) {
        __syncthreads();
        for (int i = tid; i < CH * 24; i += 128) {
            int r = i / 24, q = i % 24;
            ((uint4*)(es + r * XSTR2))[q] =
                ((const uint4*)(g_esplit + (size_t)(cbase + ch + r) * KS2))[q];
        }
        __syncthreads();

        float acc[8][8];   // [nt][mt*4 + c]
#pragma unroll
        for (int nt = 0; nt < 8; nt++)
#pragma unroll
            for (int c = 0; c < 8; c++) acc[nt][c] = 0.f;

#pragma unroll
        for (int kt = 0; kt < NKT; kt++) {
            int k0 = kt * 16 + kq * 2;
            uint32_t a[2][4];
#pragma unroll
            for (int mt = 0; mt < 2; mt++) {
                int r0 = wid * 32 + mt * 16 + g;
                a[mt][0] = *(const uint32_t*)(xs + r0 * XSTR2 + k0);
                a[mt][1] = *(const uint32_t*)(xs + (r0 + 8) * XSTR2 + k0);
                a[mt][2] = *(const uint32_t*)(xs + r0 * XSTR2 + k0 + 8);
                a[mt][3] = *(const uint32_t*)(xs + (r0 + 8) * XSTR2 + k0 + 8);
            }
#pragma unroll
            for (int nt = 0; nt < 8; nt++) {
                const __nv_bfloat16* bp = es + (nt * 8 + g) * XSTR2 + k0;
                uint32_t b0 = *(const uint32_t*)bp;
                uint32_t b1 = *(const uint32_t*)(bp + 8);
                mma16816(acc[nt] + 0, a[0], b0, b1);
                mma16816(acc[nt] + 4, a[1], b0, b1);
            }
        }

        // argmax update; code indices ascend (chunk, nt, col pair) so strict >
        // keeps first occurrence within this lane
#pragma unroll
        for (int nt = 0; nt < 8; nt++) {
            int c0 = cbase + ch + nt * 8 + kq * 2;
#pragma unroll
            for (int mt = 0; mt < 2; mt++) {
#pragma unroll
                for (int h = 0; h < 2; h++) {
                    int s = mt * 2 + h;
                    float v0 = acc[nt][mt * 4 + h * 2 + 0];
                    float v1 = acc[nt][mt * 4 + h * 2 + 1];
                    if (v0 > bv[s]) { bv[s] = v0; bi[s] = c0; }
                    if (v1 > bv[s]) { bv[s] = v1; bi[s] = c0 + 1; }
                }
            }
        }
    }

    // reduce across the 4 lanes of each row group (lower index wins ties)
#pragma unroll
    for (int s = 0; s < 4; s++) {
#pragma unroll
        for (int o = 1; o <= 2; o <<= 1) {
            float ov = __shfl_xor_sync(0xffffffffu, bv[s], o);
            int   oi = __shfl_xor_sync(0xffffffffu, bi[s], o);
            if (ov > bv[s] || (ov == bv[s] && oi < bi[s])) { bv[s] = ov; bi[s] = oi; }
        }
    }
    if (kq == 0) {
#pragma unroll
        for (int s = 0; s < 4; s++) {
            int mt = s >> 1, h = s & 1;
            int p = px0 + wid * 32 + mt * 16 + h * 8 + g;
            g_pval[blockIdx.y * PIXELS + p] = bv[s];
            g_pidx[blockIdx.y * PIXELS + p] = bi[s];
        }
    }
}

// ---------------------------------------------------------------------------
// Kernel F: reduce split partials -> closest; histogram; per-pixel loss partial.
// ---------------------------------------------------------------------------
__global__ void reduce_kernel(float* __restrict__ out)
{
    int p = blockIdx.x * 256 + threadIdx.x;
    float bv = -3.4e38f;
    int   bi = 0x7fffffff;
#pragma unroll
    for (int s = 0; s < SPLITS; s++) {
        float v = g_pval[s * PIXELS + p];
        int  ix = g_pidx[s * PIXELS + p];
        if (v > bv || (v == bv && ix < bi)) { bv = v; bi = ix; }
    }
    g_closest[p] = bi;
    out[CLOSEST_OFF + p] = (float)bi;
    atomicAdd(&g_hist[bi], 1);

    float s2 = 0.f;
    const float4* xr = (const float4*)(g_xn + (size_t)p * 32);
    const float4* er = (const float4*)(g_en + (size_t)bi * 32);
#pragma unroll
    for (int q = 0; q < 8; q++) {
        float4 x = xr[q], e = er[q];
        float d0 = x.x - e.x, d1 = x.y - e.y, d2 = x.z - e.z, d3 = x.w - e.w;
        s2 += d0 * d0; s2 += d1 * d1; s2 += d2 * d2; s2 += d3 * d3;
    }
    g_lossp[p] = s2;
}

// ---------------------------------------------------------------------------
// Kernel D: expansion GEMM: out[b,d,hw] = sum_f lat[p][f] * exp_w[d][f] + exp_b[d]
// ---------------------------------------------------------------------------
__global__ void expand_kernel(const float* __restrict__ ew,
                              const float* __restrict__ eb,
                              float* __restrict__ out)
{
    __shared__ float Wsh[64 * 32];
    __shared__ float bsh[64];
    int tid = threadIdx.x;
    int d0  = blockIdx.y * 64;

    const float4* src = (const float4*)(ew + (size_t)d0 * 32);
    float4* dst = (float4*)Wsh;
    dst[tid]       = src[tid];
    dst[tid + 256] = src[tid + 256];
    if (tid < 64) bsh[tid] = eb[d0 + tid];
    __syncthreads();

    int p  = blockIdx.x * 256 + tid;
    int b  = p >> 10;
    int hw = p & 1023;
    int idx = g_closest[p];

    float4 lat[8];
    const float4* lr = (const float4*)(g_en + (size_t)idx * 32);
#pragma unroll
    for (int q = 0; q < 8; q++) lat[q] = lr[q];

    float* outp = out + OUT_OFF + ((size_t)b * 512 + d0) * 1024 + hw;
#pragma unroll 2
    for (int dd = 0; dd < 64; dd++) {
        const float4* wr = (const float4*)(Wsh + dd * 32);
        float s = bsh[dd];
#pragma unroll
        for (int q = 0; q < 8; q++) {
            float4 w = wr[q];
            s += lat[q].x * w.x; s += lat[q].y * w.y;
            s += lat[q].z * w.z; s += lat[q].w * w.w;
        }
        outp[(size_t)dd * 1024] = s;
    }
}

// ---------------------------------------------------------------------------
// Kernel G: deterministic final reductions -> loss_q, perplexity
// ---------------------------------------------------------------------------
__global__ void finalize_kernel(float* __restrict__ out)
{
    __shared__ double sh[256];
    int tid = threadIdx.x;

    double ls = 0.0;
    for (int i = tid; i < PIXELS; i += 256) ls += (double)g_lossp[i];
    sh[tid] = ls;
    __syncthreads();
    for (int o = 128; o; o >>= 1) {
        if (tid < o) sh[tid] += sh[tid + o];
        __syncthreads();
    }
    double loss = sh[0] / (double)(PIXELS * 32);
    __syncthreads();

    double ps = 0.0;
    for (int i = tid; i < NN; i += 256) {
        float u = (float)g_hist[i] * (1.0f / 8192.0f);
        ps += -(double)u * log((double)u + 1e-6);
    }
    sh[tid] = ps;
    __syncthreads();
    for (int o = 128; o; o >>= 1) {
        if (tid < o) sh[tid] += sh[tid + o];
        __syncthreads();
    }
    if (tid == 0) {
        out[LOSS_OFF] = (float)loss;
        out[PERP_OFF] = (float)exp(sh[0]);
    }
}

// ---------------------------------------------------------------------------
extern "C" void kernel_launch(void* const* d_in, const int* in_sizes, int n_in,
                              void* d_out, int out_size)
{
    const float* enc = (const float*)d_in[0];  // [8,512,32,32]
    const float* emb = (const float*)d_in[1];  // [16384,32]
    const float* pw  = (const float*)d_in[2];  // [32,512]
    const float* pb  = (const float*)d_in[3];  // [32]
    const float* ew  = (const float*)d_in[4];  // [512,32]
    const float* eb  = (const float*)d_in[5];  // [512]
    float* out = (float*)d_out;

    (void)in_sizes; (void)n_in; (void)out_size;

    const int a_smem = (FF * DD + 32 * 33 + 32) * (int)sizeof(float); // 69888
    cudaFuncSetAttribute(proj_norm_kernel,
                         cudaFuncAttributeMaxDynamicSharedMemorySize, a_smem);

    const int c_smem = (128 + CH) * XSTR2 * (int)sizeof(__nv_bfloat16); // 76800
    cudaFuncSetAttribute(sims_argmax_kernel,
                         cudaFuncAttributeMaxDynamicSharedMemorySize, c_smem);

    proj_norm_kernel<<<256, 256, a_smem>>>(enc, pw, pb);
    enorm_kernel<<<2048, 256>>>(emb);
    sims_argmax_kernel<<<dim3(64, SPLITS), 128, c_smem>>>();
    reduce_kernel<<<32, 256>>>(out);
    expand_kernel<<<dim3(32, 8), 256>>>(ew, eb, out);
    finalize_kernel<<<1, 256>>>(out);
}

// round 7
// speedup vs baseline: 5.4224x; 1.4167x over previous
#include <cuda_runtime.h>
#include <cuda_bf16.h>
#include <cstdint>
#include <math.h>

// Problem constants
#define PIXELS 8192      // B*H*W = 8*32*32
#define DD 512
#define FF 32
#define NN 16384
#define HWSZ 1024
#define SPLITS 8
#define CPS (NN / SPLITS)   // 2048 codes per split
#define KS2 128             // 4 split blocks of 32 along K
#define NKT 8               // k16 steps per dot product
#define XSTR2 136           // smem row stride in bf16 (272B; conflict-free)
#define CH 64               // codes per chunk in kernel C

// Output layout (concatenated flattened outputs, float32):
#define OUT_OFF      0
#define CLOSEST_OFF  4194304
#define LOSS_OFF     4202496
#define PERP_OFF     4202497

// Scratch (no allocations allowed)
__device__ float g_xn[PIXELS * FF];       // normalized projected x, [p][32]
__device__ float g_en[NN * FF];           // normalized codebook, [n][32]
__device__ __nv_bfloat16 g_xsplit[PIXELS * KS2]; // [xh|xh|xm|xm]
__device__ __nv_bfloat16 g_esplit[NN * KS2];     // [eh|em|eh|em]
__device__ float g_pval[SPLITS * PIXELS]; // per-split best value
__device__ int   g_pidx[SPLITS * PIXELS]; // per-split best index
__device__ int   g_closest[PIXELS];
__device__ int   g_hist[NN];
__device__ float g_lossp[PIXELS];

// exact fp32 -> bf16 x2 split (hi + mid, residual ~2^-17 rel dropped in GEMM)
__device__ __forceinline__ void split2(float v, __nv_bfloat16& b0,
                                       __nv_bfloat16& b1)
{
    b0 = __float2bfloat16_rn(v);
    float r1 = v - __bfloat162float(b0);
    b1 = __float2bfloat16_rn(r1);
}

// ---------------------------------------------------------------------------
// Kernel A: 1x1 conv projection + channel L2 normalize + split layout.
// ---------------------------------------------------------------------------
__global__ void proj_norm_kernel(const float* __restrict__ enc,
                                 const float* __restrict__ pw,
                                 const float* __restrict__ pb)
{
    extern __shared__ float sm[];
    float* Ws  = sm;                 // 32*512
    float* xsh = sm + FF * DD;       // 32*33 (padded)
    float* nrm = xsh + 32 * 33;      // 32

    int tid = threadIdx.x;

    const float4* W4 = (const float4*)pw;
    float4* Ws4 = (float4*)Ws;
#pragma unroll
    for (int i = 0; i < 16; i++) Ws4[tid + 256 * i] = W4[tid + 256 * i];
    __syncthreads();

    int lane = tid & 31;     // pixel within tile
    int fg   = tid >> 5;     // 0..7
    int f0   = fg * 4;
    int p    = blockIdx.x * 32 + lane;
    int b    = p >> 10;
    int hw   = p & 1023;

    const float* ep = enc + (size_t)b * DD * HWSZ + hw;
    const float4* w0 = (const float4*)(Ws + (size_t)(f0 + 0) * DD);
    const float4* w1 = (const float4*)(Ws + (size_t)(f0 + 1) * DD);
    const float4* w2 = (const float4*)(Ws + (size_t)(f0 + 2) * DD);
    const float4* w3 = (const float4*)(Ws + (size_t)(f0 + 3) * DD);

    float a0 = 0.f, a1 = 0.f, a2 = 0.f, a3 = 0.f;
#pragma unroll 4
    for (int q = 0; q < 128; q++) {
        float e0 = ep[(4 * q + 0) * HWSZ];
        float e1 = ep[(4 * q + 1) * HWSZ];
        float e2 = ep[(4 * q + 2) * HWSZ];
        float e3 = ep[(4 * q + 3) * HWSZ];
        float4 W0 = w0[q], W1 = w1[q], W2 = w2[q], W3 = w3[q];
        a0 += e0 * W0.x; a0 += e1 * W0.y; a0 += e2 * W0.z; a0 += e3 * W0.w;
        a1 += e0 * W1.x; a1 += e1 * W1.y; a1 += e2 * W1.z; a1 += e3 * W1.w;
        a2 += e0 * W2.x; a2 += e1 * W2.y; a2 += e2 * W2.z; a2 += e3 * W2.w;
        a3 += e0 * W3.x; a3 += e1 * W3.y; a3 += e2 * W3.z; a3 += e3 * W3.w;
    }
    a0 += pb[f0 + 0];
    a1 += pb[f0 + 1];
    a2 += pb[f0 + 2];
    a3 += pb[f0 + 3];

    xsh[lane * 33 + f0 + 0] = a0;
    xsh[lane * 33 + f0 + 1] = a1;
    xsh[lane * 33 + f0 + 2] = a2;
    xsh[lane * 33 + f0 + 3] = a3;
    __syncthreads();

    if (tid < 32) {
        float ss = 0.f;
#pragma unroll
        for (int f = 0; f < 32; f++) { float v = xsh[tid * 33 + f]; ss += v * v; }
        nrm[tid] = fmaxf(sqrtf(ss), 1e-6f);
    }
    __syncthreads();

    float nm = nrm[lane];
    float o[4] = { a0 / nm, a1 / nm, a2 / nm, a3 / nm };
    *(float4*)(g_xn + (size_t)p * FF + f0) = *(float4*)o;

    // X split blocks: [xh | xh | xm | xm]
    __nv_bfloat16* xr = g_xsplit + (size_t)p * KS2;
#pragma unroll
    for (int k = 0; k < 4; k++) {
        __nv_bfloat16 h, m;
        split2(o[k], h, m);
        int f = f0 + k;
        xr[f]       = h;
        xr[32 + f]  = h;
        xr[64 + f]  = m;
        xr[96 + f]  = m;
    }
}

// ---------------------------------------------------------------------------
// Kernel B: codebook L2 normalize + split.
// ---------------------------------------------------------------------------
__global__ void enorm_kernel(const float* __restrict__ emb)
{
    int tid  = threadIdx.x;
    int r    = blockIdx.x * 8 + (tid >> 5);
    int lane = tid & 31;
    float v = emb[(size_t)r * 32 + lane];
    float ss = v * v;
#pragma unroll
    for (int o = 16; o; o >>= 1) ss += __shfl_xor_sync(0xffffffffu, ss, o);
    float nm = fmaxf(sqrtf(ss), 1e-6f);
    float en = v / nm;
    g_en[(size_t)r * 32 + lane] = en;

    // E split blocks: [eh | em | eh | em]
    __nv_bfloat16 h, m;
    split2(en, h, m);
    __nv_bfloat16* er = g_esplit + (size_t)r * KS2;
    er[lane]       = h;
    er[32 + lane]  = m;
    er[64 + lane]  = h;
    er[96 + lane]  = m;
}

// ---------------------------------------------------------------------------
// Kernel H: zero histogram (also shifts sims into ncu's captured launch slot)
// ---------------------------------------------------------------------------
__global__ void histzero_kernel()
{
    g_hist[blockIdx.x * 256 + threadIdx.x] = 0;
}

// ---------------------------------------------------------------------------
// mma.sync m16n8k16 row.col bf16 -> f32
// ---------------------------------------------------------------------------
__device__ __forceinline__ void mma16816(float* c, const uint32_t* a,
                                         uint32_t b0, uint32_t b1)
{
    asm volatile(
        "mma.sync.aligned.m16n8k16.row.col.f32.bf16.bf16.f32 "
        "{%0,%1,%2,%3}, {%4,%5,%6,%7}, {%8,%9}, {%0,%1,%2,%3};"
        : "+f"(c[0]), "+f"(c[1]), "+f"(c[2]), "+f"(c[3])
        : "r"(a[0]), "r"(a[1]), "r"(a[2]), "r"(a[3]), "r"(b0), "r"(b1));
}

// ---------------------------------------------------------------------------
// Kernel C (dominant): bf16 4-term split cosine sims on tensor cores
// (mma.sync) + running per-pixel argmax.
// Block 128 thr (4 warps). Block tile 128 px x 64-code chunks; warp = 32 px
// (two m16 tiles), K = 128 (8 k16 steps). grid (64 px-tiles, 8 splits).
// ---------------------------------------------------------------------------
__global__ void __launch_bounds__(128) sims_argmax_kernel()
{
    extern __shared__ __nv_bfloat16 smc[];
    __nv_bfloat16* xs = smc;                    // [128][XSTR2]
    __nv_bfloat16* es = smc + 128 * XSTR2;      // [64][XSTR2]

    int tid  = threadIdx.x;
    int wid  = tid >> 5;
    int lane = tid & 31;
    int g    = lane >> 2;   // row group / B column
    int kq   = lane & 3;    // k quad
    int px0  = blockIdx.x * 128;
    int cbase = blockIdx.y * CPS;

    // load x tile: 128 rows x 16 uint4 (256B/row)
    for (int i = tid; i < 128 * 16; i += 128) {
        int r = i >> 4, q = i & 15;
        ((uint4*)(xs + r * XSTR2))[q] =
            ((const uint4*)(g_xsplit + (size_t)(px0 + r) * KS2))[q];
    }

    float bv[4];
    int   bi[4];
#pragma unroll
    for (int s = 0; s < 4; s++) { bv[s] = -3.4e38f; bi[s] = 0; }

    for (int ch = 0; ch < CPS; ch += CH) {
        __syncthreads();
        for (int i = tid; i < CH * 16; i += 128) {
            int r = i >> 4, q = i & 15;
            ((uint4*)(es + r * XSTR2))[q] =
                ((const uint4*)(g_esplit + (size_t)(cbase + ch + r) * KS2))[q];
        }
        __syncthreads();

        float acc[8][8];   // [nt][mt*4 + c]
#pragma unroll
        for (int nt = 0; nt < 8; nt++)
#pragma unroll
            for (int c = 0; c < 8; c++) acc[nt][c] = 0.f;

#pragma unroll
        for (int kt = 0; kt < NKT; kt++) {
            int k0 = kt * 16 + kq * 2;
            uint32_t a[2][4];
#pragma unroll
            for (int mt = 0; mt < 2; mt++) {
                int r0 = wid * 32 + mt * 16 + g;
                a[mt][0] = *(const uint32_t*)(xs + r0 * XSTR2 + k0);
                a[mt][1] = *(const uint32_t*)(xs + (r0 + 8) * XSTR2 + k0);
                a[mt][2] = *(const uint32_t*)(xs + r0 * XSTR2 + k0 + 8);
                a[mt][3] = *(const uint32_t*)(xs + (r0 + 8) * XSTR2 + k0 + 8);
            }
#pragma unroll
            for (int nt = 0; nt < 8; nt++) {
                const __nv_bfloat16* bp = es + (nt * 8 + g) * XSTR2 + k0;
                uint32_t b0 = *(const uint32_t*)bp;
                uint32_t b1 = *(const uint32_t*)(bp + 8);
                mma16816(acc[nt] + 0, a[0], b0, b1);
                mma16816(acc[nt] + 4, a[1], b0, b1);
            }
        }

        // argmax update; code indices ascend (chunk, nt, col pair) so strict >
        // keeps first occurrence within this lane
#pragma unroll
        for (int nt = 0; nt < 8; nt++) {
            int c0 = cbase + ch + nt * 8 + kq * 2;
#pragma unroll
            for (int mt = 0; mt < 2; mt++) {
#pragma unroll
                for (int h = 0; h < 2; h++) {
                    int s = mt * 2 + h;
                    float v0 = acc[nt][mt * 4 + h * 2 + 0];
                    float v1 = acc[nt][mt * 4 + h * 2 + 1];
                    if (v0 > bv[s]) { bv[s] = v0; bi[s] = c0; }
                    if (v1 > bv[s]) { bv[s] = v1; bi[s] = c0 + 1; }
                }
            }
        }
    }

    // reduce across the 4 lanes of each row group (lower index wins ties)
#pragma unroll
    for (int s = 0; s < 4; s++) {
#pragma unroll
        for (int o = 1; o <= 2; o <<= 1) {
            float ov = __shfl_xor_sync(0xffffffffu, bv[s], o);
            int   oi = __shfl_xor_sync(0xffffffffu, bi[s], o);
            if (ov > bv[s] || (ov == bv[s] && oi < bi[s])) { bv[s] = ov; bi[s] = oi; }
        }
    }
    if (kq == 0) {
#pragma unroll
        for (int s = 0; s < 4; s++) {
            int mt = s >> 1, h = s & 1;
            int p = px0 + wid * 32 + mt * 16 + h * 8 + g;
            g_pval[blockIdx.y * PIXELS + p] = bv[s];
            g_pidx[blockIdx.y * PIXELS + p] = bi[s];
        }
    }
}

// ---------------------------------------------------------------------------
// Kernel F: reduce split partials -> closest; histogram; per-pixel loss partial.
// ---------------------------------------------------------------------------
__global__ void reduce_kernel(float* __restrict__ out)
{
    int p = blockIdx.x * 256 + threadIdx.x;
    float bv = -3.4e38f;
    int   bi = 0x7fffffff;
#pragma unroll
    for (int s = 0; s < SPLITS; s++) {
        float v = g_pval[s * PIXELS + p];
        int  ix = g_pidx[s * PIXELS + p];
        if (v > bv || (v == bv && ix < bi)) { bv = v; bi = ix; }
    }
    g_closest[p] = bi;
    out[CLOSEST_OFF + p] = (float)bi;
    atomicAdd(&g_hist[bi], 1);

    float s2 = 0.f;
    const float4* xr = (const float4*)(g_xn + (size_t)p * 32);
    const float4* er = (const float4*)(g_en + (size_t)bi * 32);
#pragma unroll
    for (int q = 0; q < 8; q++) {
        float4 x = xr[q], e = er[q];
        float d0 = x.x - e.x, d1 = x.y - e.y, d2 = x.z - e.z, d3 = x.w - e.w;
        s2 += d0 * d0; s2 += d1 * d1; s2 += d2 * d2; s2 += d3 * d3;
    }
    g_lossp[p] = s2;
}

// ---------------------------------------------------------------------------
// Kernel D: expansion GEMM: out[b,d,hw] = sum_f lat[p][f] * exp_w[d][f] + exp_b[d]
// ---------------------------------------------------------------------------
__global__ void expand_kernel(const float* __restrict__ ew,
                              const float* __restrict__ eb,
                              float* __restrict__ out)
{
    __shared__ float Wsh[64 * 32];
    __shared__ float bsh[64];
    int tid = threadIdx.x;
    int d0  = blockIdx.y * 64;

    const float4* src = (const float4*)(ew + (size_t)d0 * 32);
    float4* dst = (float4*)Wsh;
    dst[tid]       = src[tid];
    dst[tid + 256] = src[tid + 256];
    if (tid < 64) bsh[tid] = eb[d0 + tid];
    __syncthreads();

    int p  = blockIdx.x * 256 + tid;
    int b  = p >> 10;
    int hw = p & 1023;
    int idx = g_closest[p];

    float4 lat[8];
    const float4* lr = (const float4*)(g_en + (size_t)idx * 32);
#pragma unroll
    for (int q = 0; q < 8; q++) lat[q] = lr[q];

    float* outp = out + OUT_OFF + ((size_t)b * 512 + d0) * 1024 + hw;
#pragma unroll 2
    for (int dd = 0; dd < 64; dd++) {
        const float4* wr = (const float4*)(Wsh + dd * 32);
        float s = bsh[dd];
#pragma unroll
        for (int q = 0; q < 8; q++) {
            float4 w = wr[q];
            s += lat[q].x * w.x; s += lat[q].y * w.y;
            s += lat[q].z * w.z; s += lat[q].w * w.w;
        }
        outp[(size_t)dd * 1024] = s;
    }
}

// ---------------------------------------------------------------------------
// Kernel G: deterministic final reductions -> loss_q, perplexity
// ---------------------------------------------------------------------------
__global__ void finalize_kernel(float* __restrict__ out)
{
    __shared__ double sh[256];
    int tid = threadIdx.x;

    double ls = 0.0;
    for (int i = tid; i < PIXELS; i += 256) ls += (double)g_lossp[i];
    sh[tid] = ls;
    __syncthreads();
    for (int o = 128; o; o >>= 1) {
        if (tid < o) sh[tid] += sh[tid + o];
        __syncthreads();
    }
    double loss = sh[0] / (double)(PIXELS * 32);
    __syncthreads();

    double ps = 0.0;
    for (int i = tid; i < NN; i += 256) {
        float u = (float)g_hist[i] * (1.0f / 8192.0f);
        ps += -(double)u * log((double)u + 1e-6);
    }
    sh[tid] = ps;
    __syncthreads();
    for (int o = 128; o; o >>= 1) {
        if (tid < o) sh[tid] += sh[tid + o];
        __syncthreads();
    }
    if (tid == 0) {
        out[LOSS_OFF] = (float)loss;
        out[PERP_OFF] = (float)exp(sh[0]);
    }
}

// ---------------------------------------------------------------------------
extern "C" void kernel_launch(void* const* d_in, const int* in_sizes, int n_in,
                              void* d_out, int out_size)
{
    const float* enc = (const float*)d_in[0];  // [8,512,32,32]
    const float* emb = (const float*)d_in[1];  // [16384,32]
    const float* pw  = (const float*)d_in[2];  // [32,512]
    const float* pb  = (const float*)d_in[3];  // [32]
    const float* ew  = (const float*)d_in[4];  // [512,32]
    const float* eb  = (const float*)d_in[5];  // [512]
    float* out = (float*)d_out;

    (void)in_sizes; (void)n_in; (void)out_size;

    const int a_smem = (FF * DD + 32 * 33 + 32) * (int)sizeof(float); // 69888
    cudaFuncSetAttribute(proj_norm_kernel,
                         cudaFuncAttributeMaxDynamicSharedMemorySize, a_smem);

    const int c_smem = (128 + CH) * XSTR2 * (int)sizeof(__nv_bfloat16); // 52224
    cudaFuncSetAttribute(sims_argmax_kernel,
                         cudaFuncAttributeMaxDynamicSharedMemorySize, c_smem);

    proj_norm_kernel<<<256, 256, a_smem>>>(enc, pw, pb);
    enorm_kernel<<<2048, 256>>>(emb);
    histzero_kernel<<<64, 256>>>();
    sims_argmax_kernel<<<dim3(64, SPLITS), 128, c_smem>>>();
    reduce_kernel<<<32, 256>>>(out);
    expand_kernel<<<dim3(32, 8), 256>>>(ew, eb, out);
    finalize_kernel<<<1, 256>>>(out);
}